// round 7
// baseline (speedup 1.0000x reference)
#include <cuda_runtime.h>
#include <cuda_fp16.h>
#include <cstdint>

// ============================================================================
// QuantLinear: y = x @ (scales*q - zeros) + bias        (sm_100 portable path)
//   x:[32,4096] f32, qweight:[512,11008] i32 (8 nibbles/word along K),
//   scales/zeros/bias:[11008] f32, out:[32,11008] f32
//
// Fully fused single GEMM kernel (plus one cudaMemsetAsync to zero out):
//   grid (86, 3): N tiles of 128 x K splits of 11/11/10 chunks of 128.
//   - A: each CTA converts its x slice f32->fp16 (permuted (0,4,1,5,2,6,3,7)
//     within groups of 8, SW-swizzled) straight into smem; x is L2-hot and
//     prefetched one chunk ahead in registers. Also accumulates per-split
//     row sums S_sp on the fly.
//   - Q: 3-slot cp.async pipeline (depth 2).
//   - mma.m16n8k16 fp16->f32; B dequant: ((w>>4*j4)&0x000F000F)|0x64006400.
//   - Epilogue per split: atomicAdd(out, s*D_sp - S_sp*(1024*s+z) [+ b]).
// ============================================================================

#define KTOT   4096
#define NTOT   11008
#define MTOK   32
#define TILE_N 128
#define TILE_K 128
#define KSPLIT 3
#define THREADS 256

#define SM_A   0                  // 8192 B  (32 rows x 256B, single buffer)
#define SM_Q   8192               // 3 slots x 8192 B
#define SM_S   32768              // 32 floats
#define SMEM_TOTAL 32896

// ---------------------------------------------------------------------------
__device__ __forceinline__ uint32_t smem_u32(const void* p) {
    uint32_t a;
    asm("{ .reg .u64 t; cvta.to.shared.u64 t, %1; cvt.u32.u64 %0, t; }"
        : "=r"(a) : "l"(p));
    return a;
}

#define CP16(dst, src) \
    asm volatile("cp.async.cg.shared.global [%0], [%1], 16;" :: "r"(dst), "l"(src))
#define CP_COMMIT() asm volatile("cp.async.commit_group;" ::: "memory")

__device__ __forceinline__ void mma16816(float* d, const uint32_t* a,
                                         uint32_t b0, uint32_t b1) {
    asm volatile(
        "mma.sync.aligned.m16n8k16.row.col.f32.f16.f16.f32 "
        "{%0,%1,%2,%3}, {%4,%5,%6,%7}, {%8,%9}, {%0,%1,%2,%3};"
        : "+f"(d[0]), "+f"(d[1]), "+f"(d[2]), "+f"(d[3])
        : "r"(a[0]), "r"(a[1]), "r"(a[2]), "r"(a[3]), "r"(b0), "r"(b1));
}

__device__ __forceinline__ void ldmx4(uint32_t* a, uint32_t addr) {
    asm volatile("ldmatrix.sync.aligned.m8n8.x4.shared.b16 {%0,%1,%2,%3}, [%4];"
                 : "=r"(a[0]), "=r"(a[1]), "=r"(a[2]), "=r"(a[3]) : "r"(addr));
}

__device__ __forceinline__ uint32_t pack2(__half a, __half b) {
    return (uint32_t)__half_as_ushort(a) | ((uint32_t)__half_as_ushort(b) << 16);
}

// ---------------------------------------------------------------------------
__device__ __forceinline__ void issue_q(uint32_t sb, int tid, int n0, int slot,
                                        int cg, const int* __restrict__ qw) {
    uint32_t stage = sb + SM_Q + (uint32_t)slot * 8192;
    #pragma unroll
    for (int i = 0; i < 2; i++) {
        int seg = tid + i * 256;
        int kw = seg >> 5, ns = seg & 31;
        uint32_t dst = stage + kw * 512 + ns * 16;
        const char* src = (const char*)qw + ((size_t)(cg * 16 + kw) * NTOT + n0) * 4 + ns * 16;
        CP16(dst, src);
    }
    CP_COMMIT();
}

__global__ void __launch_bounds__(THREADS, 2) gemm_kernel(
    const float* __restrict__ x, const int* __restrict__ qw,
    const float* __restrict__ scales, const float* __restrict__ zeros,
    const float* __restrict__ bias, float* __restrict__ out) {
    extern __shared__ __align__(1024) char smem[];
    uint32_t sb = smem_u32(smem);
    int tid = threadIdx.x, wid = tid >> 5, lane = tid & 31;
    int n0 = blockIdx.x * TILE_N;
    int kb = blockIdx.y * 11;                  // splits: 11 / 11 / 10
    int nc = (blockIdx.y == 2) ? 10 : 11;
    float* S_sm = (float*)(smem + SM_S);

    // ---- A conversion ownership: row = tid>>3, 16 k's at oct = tid&7 ----
    const int arow = tid >> 3;
    const int oct  = tid & 7;
    const float* xrow = x + (size_t)arow * KTOT + oct * 16;

    // prologue: prefetch x for chunk 0; Q for chunks 0,1
    float4 v[4];
    {
        const float4* p = (const float4*)(xrow + kb * TILE_K);
        v[0] = p[0]; v[1] = p[1]; v[2] = p[2]; v[3] = p[3];
    }
    issue_q(sb, tid, n0, 0, kb + 0, qw);
    issue_q(sb, tid, n0, 1, kb + 1, qw);

    const int lrow = lane & 15;
    const int lcb  = lane >> 4;
    const int j4   = lane & 3;
    const int nrow = lane >> 2;
    const uint32_t sh4 = (uint32_t)(j4 * 4);

    float acc[2][2][4];
    #pragma unroll
    for (int mt = 0; mt < 2; mt++)
        #pragma unroll
        for (int j = 0; j < 2; j++)
            #pragma unroll
            for (int i = 0; i < 4; i++) acc[mt][j][i] = 0.f;

    float accS = 0.f;

    for (int c = 0; c < nc; c++) {
        if (c < nc - 1) asm volatile("cp.async.wait_group 1;" ::: "memory");
        else            asm volatile("cp.async.wait_group 0;" ::: "memory");
        __syncthreads();                 // Q(c) ready; prev compute done (A safe)

        // convert + permute chunk c's A into smem, accumulate S
        {
            float f[16] = {v[0].x, v[0].y, v[0].z, v[0].w,
                           v[1].x, v[1].y, v[1].z, v[1].w,
                           v[2].x, v[2].y, v[2].z, v[2].w,
                           v[3].x, v[3].y, v[3].z, v[3].w};
            #pragma unroll
            for (int g = 0; g < 2; g++) {
                __half h[8];
                #pragma unroll
                for (int j = 0; j < 8; j++) {
                    h[j] = __float2half(f[g * 8 + j]);
                    accS += __half2float(h[j]);
                }
                uint4 o;
                o.x = pack2(h[0], h[4]);
                o.y = pack2(h[1], h[5]);
                o.z = pack2(h[2], h[6]);
                o.w = pack2(h[3], h[7]);
                uint32_t cc = (uint32_t)(oct * 2 + g);
                uint32_t dst = sb + SM_A + arow * 256 + ((cc ^ (uint32_t)(arow & 7)) << 4);
                asm volatile("st.shared.v4.b32 [%0], {%1,%2,%3,%4};"
                             :: "r"(dst), "r"(o.x), "r"(o.y), "r"(o.z), "r"(o.w));
            }
        }
        // prefetch x for chunk c+1 (L2-hot; hides behind compute below)
        if (c + 1 < nc) {
            const float4* p = (const float4*)(xrow + (kb + c + 1) * TILE_K);
            v[0] = p[0]; v[1] = p[1]; v[2] = p[2]; v[3] = p[3];
        }
        __syncthreads();                 // A(c) visible
        if (c + 2 < nc) issue_q(sb, tid, n0, (c + 2) % 3, kb + c + 2, qw);

        uint32_t aBase = sb + SM_A;
        uint32_t qBase = sb + SM_Q + (uint32_t)(c % 3) * 8192;
        uint32_t q0 = qBase + (uint32_t)(wid * 16 + nrow) * 4;   // j=0 n-slice
        uint32_t q1 = q0 + 8 * 4;                                 // j=1 n-slice

        #pragma unroll
        for (int kk = 0; kk < 8; kk++) {
            uint32_t a0[4], a1[4];
            uint32_t cc = (uint32_t)(kk * 2 + lcb);
            uint32_t ad0 = aBase + (uint32_t)lrow * 256 + ((cc ^ (uint32_t)(lrow & 7)) << 4);
            ldmx4(a0, ad0);
            ldmx4(a1, ad0 + 16 * 256);

            uint32_t w00, w01, w10, w11;
            asm volatile("ld.shared.b32 %0, [%1];" : "=r"(w00) : "r"(q0 + kk * 1024));
            asm volatile("ld.shared.b32 %0, [%1];" : "=r"(w01) : "r"(q0 + kk * 1024 + 512));
            asm volatile("ld.shared.b32 %0, [%1];" : "=r"(w10) : "r"(q1 + kk * 1024));
            asm volatile("ld.shared.b32 %0, [%1];" : "=r"(w11) : "r"(q1 + kk * 1024 + 512));

            uint32_t b00 = ((w00 >> sh4) & 0x000F000Fu) | 0x64006400u;
            uint32_t b01 = ((w01 >> sh4) & 0x000F000Fu) | 0x64006400u;
            uint32_t b10 = ((w10 >> sh4) & 0x000F000Fu) | 0x64006400u;
            uint32_t b11 = ((w11 >> sh4) & 0x000F000Fu) | 0x64006400u;

            mma16816(acc[0][0], a0, b00, b01);
            mma16816(acc[1][0], a1, b00, b01);
            mma16816(acc[0][1], a0, b10, b11);
            mma16816(acc[1][1], a1, b10, b11);
        }
    }

    // ---- reduce S over the 8 threads of each row ----
    #pragma unroll
    for (int off = 4; off; off >>= 1) accS += __shfl_xor_sync(0xFFFFFFFFu, accS, off);
    if (oct == 0) S_sm[arow] = accS;
    __syncthreads();

    // ---- epilogue: out += s*D - S_sp*(1024*s + z) [+ b on split 0] ----
    const bool first = (blockIdx.y == 0);
    #pragma unroll
    for (int mt = 0; mt < 2; mt++) {
        #pragma unroll
        for (int j = 0; j < 2; j++) {
            int ncl = wid * 16 + j * 8 + j4 * 2;
            int col = n0 + ncl;
            float s0 = __ldg(scales + col), s1 = __ldg(scales + col + 1);
            float z0 = __ldg(zeros + col),  z1 = __ldg(zeros + col + 1);
            float c0 = fmaf(1024.f, s0, z0);
            float c1 = fmaf(1024.f, s1, z1);
            float b0 = first ? __ldg(bias + col)     : 0.f;
            float b1 = first ? __ldg(bias + col + 1) : 0.f;
            int r0 = mt * 16 + nrow;
            int r1 = r0 + 8;
            float S0 = S_sm[r0], S1 = S_sm[r1];
            atomicAdd(out + (size_t)r0 * NTOT + col,     fmaf(s0, acc[mt][j][0], b0) - S0 * c0);
            atomicAdd(out + (size_t)r0 * NTOT + col + 1, fmaf(s1, acc[mt][j][1], b1) - S0 * c1);
            atomicAdd(out + (size_t)r1 * NTOT + col,     fmaf(s0, acc[mt][j][2], b0) - S1 * c0);
            atomicAdd(out + (size_t)r1 * NTOT + col + 1, fmaf(s1, acc[mt][j][3], b1) - S1 * c1);
        }
    }
}

// ---------------------------------------------------------------------------
extern "C" void kernel_launch(void* const* d_in, const int* in_sizes, int n_in,
                              void* d_out, int out_size) {
    const float* x      = (const float*)d_in[0];
    const int*   qw     = (const int*)d_in[1];
    const float* scales = (const float*)d_in[2];
    const float* zeros  = (const float*)d_in[3];
    const float* bias   = (const float*)d_in[4];
    float* out = (float*)d_out;

    cudaFuncSetAttribute(gemm_kernel, cudaFuncAttributeMaxDynamicSharedMemorySize, SMEM_TOTAL);

    cudaMemsetAsync(out, 0, (size_t)out_size * sizeof(float));
    gemm_kernel<<<dim3(NTOT / TILE_N, KSPLIT), THREADS, SMEM_TOTAL>>>(
        x, qw, scales, zeros, bias, out);
}

// round 8
// speedup vs baseline: 1.2993x; 1.2993x over previous
#include <cuda_runtime.h>
#include <cuda_fp16.h>
#include <cstdint>

// ============================================================================
// QuantLinear: y = x @ (scales*q - zeros) + bias        (sm_100 portable path)
//   x:[32,4096] f32, qweight:[512,11008] i32 (8 nibbles/word along K),
//   scales/zeros/bias:[11008] f32, out:[32,11008] f32
//
//   memset: out = 0
//   prep:   g_A[32,4096] = fp16(x), columns permuted within groups of 8 as
//           (0,4,1,5,2,6,3,7) in registers, 16B stores; partial row sums ->
//           g_Spart[128] (4 per token).
//   gemm:   grid (86,3): N tiles of 128 x K splits of 11/11/10 chunks.
//           mma.m16n8k16 fp16->f32; register-double-buffered kk pipeline;
//           B dequant: ((w>>4*j4)&0x000F000F)|0x64006400 (2 ops/reg).
//           Epilogue: atomicAdd(out, s*D [+ b - S*(1024*s+z) on split 0]).
// ============================================================================

#define KTOT   4096
#define NTOT   11008
#define MTOK   32
#define TILE_N 128
#define TILE_K 128
#define KSPLIT 3
#define THREADS 256
#define STAGES 3

#define STAGE_BYTES 16384         // A 8192 + Q 8192
#define SM_S (STAGES * STAGE_BYTES)
#define SMEM_TOTAL (SM_S + 128)   // + S[32]

__device__ __half g_A[MTOK * KTOT];
__device__ float  g_Spart[128];   // 4 partials per token

// ---------------------------------------------------------------------------
__device__ __forceinline__ uint32_t smem_u32(const void* p) {
    uint32_t a;
    asm("{ .reg .u64 t; cvta.to.shared.u64 t, %1; cvt.u32.u64 %0, t; }"
        : "=r"(a) : "l"(p));
    return a;
}

#define CP16(dst, src) \
    asm volatile("cp.async.cg.shared.global [%0], [%1], 16;" :: "r"(dst), "l"(src))
#define CP_COMMIT() asm volatile("cp.async.commit_group;" ::: "memory")

__device__ __forceinline__ void mma16816(float* d, const uint32_t* a,
                                         uint32_t b0, uint32_t b1) {
    asm volatile(
        "mma.sync.aligned.m16n8k16.row.col.f32.f16.f16.f32 "
        "{%0,%1,%2,%3}, {%4,%5,%6,%7}, {%8,%9}, {%0,%1,%2,%3};"
        : "+f"(d[0]), "+f"(d[1]), "+f"(d[2]), "+f"(d[3])
        : "r"(a[0]), "r"(a[1]), "r"(a[2]), "r"(a[3]), "r"(b0), "r"(b1));
}

__device__ __forceinline__ void ldmx4(uint32_t* a, uint32_t addr) {
    asm volatile("ldmatrix.sync.aligned.m8n8.x4.shared.b16 {%0,%1,%2,%3}, [%4];"
                 : "=r"(a[0]), "=r"(a[1]), "=r"(a[2]), "=r"(a[3]) : "r"(addr));
}

__device__ __forceinline__ uint32_t lds32(uint32_t addr) {
    uint32_t v;
    asm volatile("ld.shared.b32 %0, [%1];" : "=r"(v) : "r"(addr));
    return v;
}

// ---------------------------------------------------------------------------
// prep: 128 blocks (32 tokens x 4 slices) x 128 threads; thread = one group
// of 8 k-values -> permute in registers, one 16B coalesced store.
// ---------------------------------------------------------------------------
__global__ void __launch_bounds__(128, 4) prep_kernel(const float* __restrict__ x) {
    int t = blockIdx.x >> 2, sl = blockIdx.x & 3, tid = threadIdx.x;
    int k0 = sl * 1024 + tid * 8;
    const float4* src = (const float4*)(x + (size_t)t * KTOT + k0);
    float4 v0 = src[0];
    float4 v1 = src[1];
    __half h0 = __float2half(v0.x), h1 = __float2half(v0.y);
    __half h2 = __float2half(v0.z), h3 = __float2half(v0.w);
    __half h4 = __float2half(v1.x), h5 = __float2half(v1.y);
    __half h6 = __float2half(v1.z), h7 = __float2half(v1.w);
    float acc = __half2float(h0) + __half2float(h1) + __half2float(h2) +
                __half2float(h3) + __half2float(h4) + __half2float(h5) +
                __half2float(h6) + __half2float(h7);
    uint4 o;
    o.x = (uint32_t)__half_as_ushort(h0) | ((uint32_t)__half_as_ushort(h4) << 16);
    o.y = (uint32_t)__half_as_ushort(h1) | ((uint32_t)__half_as_ushort(h5) << 16);
    o.z = (uint32_t)__half_as_ushort(h2) | ((uint32_t)__half_as_ushort(h6) << 16);
    o.w = (uint32_t)__half_as_ushort(h3) | ((uint32_t)__half_as_ushort(h7) << 16);
    *(uint4*)(g_A + (size_t)t * KTOT + k0) = o;

    __shared__ float red[4];
    #pragma unroll
    for (int off = 16; off; off >>= 1) acc += __shfl_down_sync(0xFFFFFFFFu, acc, off);
    if ((tid & 31) == 0) red[tid >> 5] = acc;
    __syncthreads();
    if (tid == 0)
        g_Spart[blockIdx.x] = red[0] + red[1] + red[2] + red[3];
}

// ---------------------------------------------------------------------------
// gemm
// ---------------------------------------------------------------------------
__device__ __forceinline__ void issue_chunk(uint32_t sb, int tid, int n0,
                                            int slot, int cg,
                                            const int* __restrict__ qw) {
    uint32_t stage = sb + (uint32_t)slot * STAGE_BYTES;
    // A: 32 rows x 16 chunks of 16B (swizzled)
    #pragma unroll
    for (int i = 0; i < 2; i++) {
        int seg = tid + i * 256;
        int r = seg >> 4, cc = seg & 15;
        uint32_t dst = stage + r * 256 + (((uint32_t)cc ^ (uint32_t)(r & 7)) << 4);
        const char* src = (const char*)g_A + ((size_t)r * KTOT + (size_t)cg * TILE_K) * 2 + cc * 16;
        CP16(dst, src);
    }
    // Q: 16 kwords x 32 segs of 16B
    #pragma unroll
    for (int i = 0; i < 2; i++) {
        int seg = tid + i * 256;
        int kw = seg >> 5, ns = seg & 31;
        uint32_t dst = stage + 8192 + kw * 512 + ns * 16;
        const char* src = (const char*)qw + ((size_t)(cg * 16 + kw) * NTOT + n0) * 4 + ns * 16;
        CP16(dst, src);
    }
    CP_COMMIT();
}

__global__ void __launch_bounds__(THREADS, 2) gemm_kernel(
    const int* __restrict__ qw, const float* __restrict__ scales,
    const float* __restrict__ zeros, const float* __restrict__ bias,
    float* __restrict__ out) {
    extern __shared__ __align__(1024) char smem[];
    uint32_t sb = smem_u32(smem);
    int tid = threadIdx.x, wid = tid >> 5, lane = tid & 31;
    int n0 = blockIdx.x * TILE_N;
    int kb = blockIdx.y * 11;                       // splits: 11 / 11 / 10
    int nc = (blockIdx.y == 2) ? 10 : 11;
    float* S_sm = (float*)(smem + SM_S);

    if (tid < 32)
        S_sm[tid] = g_Spart[tid * 4] + g_Spart[tid * 4 + 1] +
                    g_Spart[tid * 4 + 2] + g_Spart[tid * 4 + 3];

    issue_chunk(sb, tid, n0, 0, kb + 0, qw);
    issue_chunk(sb, tid, n0, 1, kb + 1, qw);

    const int lrow = lane & 15;
    const int lcb  = lane >> 4;
    const int j4   = lane & 3;
    const int nrow = lane >> 2;
    const uint32_t sh4 = (uint32_t)(j4 * 4);

    float acc[2][2][4];
    #pragma unroll
    for (int mt = 0; mt < 2; mt++)
        #pragma unroll
        for (int j = 0; j < 2; j++)
            #pragma unroll
            for (int i = 0; i < 4; i++) acc[mt][j][i] = 0.f;

    for (int c = 0; c < nc; c++) {
        if (c < nc - 1) asm volatile("cp.async.wait_group 1;" ::: "memory");
        else            asm volatile("cp.async.wait_group 0;" ::: "memory");
        __syncthreads();
        if (c + 2 < nc) issue_chunk(sb, tid, n0, (c + 2) % STAGES, kb + c + 2, qw);

        uint32_t aBase = sb + (uint32_t)(c % STAGES) * STAGE_BYTES;
        uint32_t qBase = aBase + 8192;
        uint32_t q0 = qBase + (uint32_t)(wid * 16 + nrow) * 4;   // j=0 n-slice
        uint32_t q1 = q0 + 8 * 4;                                 // j=1 n-slice
        uint32_t aRow = aBase + (uint32_t)lrow * 256;

        // register double-buffered kk pipeline
        uint32_t a0[2][4], a1[2][4], w[2][4];
        {
            uint32_t cc = (uint32_t)lcb;
            uint32_t ad = aRow + ((cc ^ (uint32_t)(lrow & 7)) << 4);
            ldmx4(a0[0], ad);
            ldmx4(a1[0], ad + 16 * 256);
            w[0][0] = lds32(q0);
            w[0][1] = lds32(q0 + 512);
            w[0][2] = lds32(q1);
            w[0][3] = lds32(q1 + 512);
        }
        #pragma unroll
        for (int kk = 0; kk < 8; kk++) {
            int cur = kk & 1, nx = cur ^ 1;
            if (kk < 7) {
                uint32_t cc = (uint32_t)((kk + 1) * 2 + lcb);
                uint32_t ad = aRow + ((cc ^ (uint32_t)(lrow & 7)) << 4);
                ldmx4(a0[nx], ad);
                ldmx4(a1[nx], ad + 16 * 256);
                w[nx][0] = lds32(q0 + (kk + 1) * 1024);
                w[nx][1] = lds32(q0 + (kk + 1) * 1024 + 512);
                w[nx][2] = lds32(q1 + (kk + 1) * 1024);
                w[nx][3] = lds32(q1 + (kk + 1) * 1024 + 512);
            }
            uint32_t b00 = ((w[cur][0] >> sh4) & 0x000F000Fu) | 0x64006400u;
            uint32_t b01 = ((w[cur][1] >> sh4) & 0x000F000Fu) | 0x64006400u;
            uint32_t b10 = ((w[cur][2] >> sh4) & 0x000F000Fu) | 0x64006400u;
            uint32_t b11 = ((w[cur][3] >> sh4) & 0x000F000Fu) | 0x64006400u;

            mma16816(acc[0][0], a0[cur], b00, b01);
            mma16816(acc[1][0], a1[cur], b00, b01);
            mma16816(acc[0][1], a0[cur], b10, b11);
            mma16816(acc[1][1], a1[cur], b10, b11);
        }
    }

    // ---- epilogue: out += s*D [+ b - S*(1024*s+z) on split 0] ----
    const bool first = (blockIdx.y == 0);
    #pragma unroll
    for (int mt = 0; mt < 2; mt++) {
        #pragma unroll
        for (int j = 0; j < 2; j++) {
            int ncl = wid * 16 + j * 8 + j4 * 2;
            int col = n0 + ncl;
            float s0 = __ldg(scales + col), s1 = __ldg(scales + col + 1);
            int r0 = mt * 16 + nrow;
            int r1 = r0 + 8;
            float v00 = s0 * acc[mt][j][0];
            float v01 = s1 * acc[mt][j][1];
            float v10 = s0 * acc[mt][j][2];
            float v11 = s1 * acc[mt][j][3];
            if (first) {
                float c0 = fmaf(1024.f, s0, __ldg(zeros + col));
                float c1 = fmaf(1024.f, s1, __ldg(zeros + col + 1));
                float b0 = __ldg(bias + col);
                float b1 = __ldg(bias + col + 1);
                float S0 = S_sm[r0], S1 = S_sm[r1];
                v00 += b0 - S0 * c0;
                v01 += b1 - S0 * c1;
                v10 += b0 - S1 * c0;
                v11 += b1 - S1 * c1;
            }
            atomicAdd(out + (size_t)r0 * NTOT + col,     v00);
            atomicAdd(out + (size_t)r0 * NTOT + col + 1, v01);
            atomicAdd(out + (size_t)r1 * NTOT + col,     v10);
            atomicAdd(out + (size_t)r1 * NTOT + col + 1, v11);
        }
    }
}

// ---------------------------------------------------------------------------
extern "C" void kernel_launch(void* const* d_in, const int* in_sizes, int n_in,
                              void* d_out, int out_size) {
    const float* x      = (const float*)d_in[0];
    const int*   qw     = (const int*)d_in[1];
    const float* scales = (const float*)d_in[2];
    const float* zeros  = (const float*)d_in[3];
    const float* bias   = (const float*)d_in[4];
    float* out = (float*)d_out;

    cudaFuncSetAttribute(gemm_kernel, cudaFuncAttributeMaxDynamicSharedMemorySize, SMEM_TOTAL);

    cudaMemsetAsync(out, 0, (size_t)out_size * sizeof(float));
    prep_kernel<<<128, 128>>>(x);
    gemm_kernel<<<dim3(NTOT / TILE_N, KSPLIT), THREADS, SMEM_TOTAL>>>(
        qw, scales, zeros, bias, out);
}

// round 9
// speedup vs baseline: 1.4290x; 1.0998x over previous
#include <cuda_runtime.h>
#include <cuda_fp16.h>
#include <cstdint>

// ============================================================================
// QuantLinear: y = x @ (scales*q - zeros) + bias        (sm_100 portable path)
//   x:[32,4096] f32, qweight:[512,11008] i32 (8 nibbles/word along K),
//   scales/zeros/bias:[11008] f32, out:[32,11008] f32
//
//   prep:  g_A[32,4096] = fp16(x) permuted (0,4,1,5,2,6,3,7) within groups of
//          8; partial row sums -> g_Spart[128]; ALSO zeroes out[].
//   gemm:  persistent-balanced: 2752 (ntile,chunk) units spread contiguously
//          over exactly 296 CTAs (2 per SM). 4-stage cp.async pipeline,
//          depth-3 prefetch. mma.m16n8k16 fp16->f32; B dequant
//          ((w>>4*j4)&0x000F000F)|0x64006400. Epilogue flush per tile
//          segment: atomicAdd(out, s*D [+ b - S*(1024*s+z) if segment owns
//          chunk 0]).
// ============================================================================

#define KTOT   4096
#define NTOT   11008
#define MTOK   32
#define TILE_N 128
#define TILE_K 128
#define NCHUNK 32                 // K chunks per ntile
#define NTILES 86
#define UNITS  (NTILES * NCHUNK)  // 2752
#define GRID   296                // 2 x 148 SMs
#define THREADS 256
#define STAGES 4

#define STAGE_BYTES 16384         // A 8192 + Q 8192
#define SM_S (STAGES * STAGE_BYTES)
#define SMEM_TOTAL (SM_S + 128)   // + S[32]

#define OUTN (MTOK * NTOT)        // 352256

__device__ __half g_A[MTOK * KTOT];
__device__ float  g_Spart[128];   // 4 partials per token

// ---------------------------------------------------------------------------
__device__ __forceinline__ uint32_t smem_u32(const void* p) {
    uint32_t a;
    asm("{ .reg .u64 t; cvta.to.shared.u64 t, %1; cvt.u32.u64 %0, t; }"
        : "=r"(a) : "l"(p));
    return a;
}

#define CP16(dst, src) \
    asm volatile("cp.async.cg.shared.global [%0], [%1], 16;" :: "r"(dst), "l"(src))
#define CP_COMMIT() asm volatile("cp.async.commit_group;" ::: "memory")

__device__ __forceinline__ void mma16816(float* d, const uint32_t* a,
                                         uint32_t b0, uint32_t b1) {
    asm volatile(
        "mma.sync.aligned.m16n8k16.row.col.f32.f16.f16.f32 "
        "{%0,%1,%2,%3}, {%4,%5,%6,%7}, {%8,%9}, {%0,%1,%2,%3};"
        : "+f"(d[0]), "+f"(d[1]), "+f"(d[2]), "+f"(d[3])
        : "r"(a[0]), "r"(a[1]), "r"(a[2]), "r"(a[3]), "r"(b0), "r"(b1));
}

__device__ __forceinline__ void ldmx4(uint32_t* a, uint32_t addr) {
    asm volatile("ldmatrix.sync.aligned.m8n8.x4.shared.b16 {%0,%1,%2,%3}, [%4];"
                 : "=r"(a[0]), "=r"(a[1]), "=r"(a[2]), "=r"(a[3]) : "r"(addr));
}

__device__ __forceinline__ uint32_t lds32(uint32_t addr) {
    uint32_t v;
    asm volatile("ld.shared.b32 %0, [%1];" : "=r"(v) : "r"(addr));
    return v;
}

// ---------------------------------------------------------------------------
// prep: fp16-convert + permute x, partial row sums, and zero out[].
// ---------------------------------------------------------------------------
__global__ void __launch_bounds__(128, 4) prep_kernel(const float* __restrict__ x,
                                                      float* __restrict__ out) {
    int t = blockIdx.x >> 2, sl = blockIdx.x & 3, tid = threadIdx.x;
    int k0 = sl * 1024 + tid * 8;
    const float4* src = (const float4*)(x + (size_t)t * KTOT + k0);
    float4 v0 = src[0];
    float4 v1 = src[1];
    __half h0 = __float2half(v0.x), h1 = __float2half(v0.y);
    __half h2 = __float2half(v0.z), h3 = __float2half(v0.w);
    __half h4 = __float2half(v1.x), h5 = __float2half(v1.y);
    __half h6 = __float2half(v1.z), h7 = __float2half(v1.w);
    float acc = __half2float(h0) + __half2float(h1) + __half2float(h2) +
                __half2float(h3) + __half2float(h4) + __half2float(h5) +
                __half2float(h6) + __half2float(h7);
    uint4 o;
    o.x = (uint32_t)__half_as_ushort(h0) | ((uint32_t)__half_as_ushort(h4) << 16);
    o.y = (uint32_t)__half_as_ushort(h1) | ((uint32_t)__half_as_ushort(h5) << 16);
    o.z = (uint32_t)__half_as_ushort(h2) | ((uint32_t)__half_as_ushort(h6) << 16);
    o.w = (uint32_t)__half_as_ushort(h3) | ((uint32_t)__half_as_ushort(h7) << 16);
    *(uint4*)(g_A + (size_t)t * KTOT + k0) = o;

    // zero out[] (float4 strided over all prep threads)
    int gtid = blockIdx.x * 128 + tid;
    const float4 z4 = {0.f, 0.f, 0.f, 0.f};
    for (int i = gtid; i < OUTN / 4; i += 128 * 128)
        ((float4*)out)[i] = z4;

    __shared__ float red[4];
    #pragma unroll
    for (int off = 16; off; off >>= 1) acc += __shfl_down_sync(0xFFFFFFFFu, acc, off);
    if ((tid & 31) == 0) red[tid >> 5] = acc;
    __syncthreads();
    if (tid == 0)
        g_Spart[blockIdx.x] = red[0] + red[1] + red[2] + red[3];
}

// ---------------------------------------------------------------------------
// gemm (persistent balanced)
// ---------------------------------------------------------------------------
__device__ __forceinline__ void issue_unit(uint32_t sb, int tid, int u, int slot,
                                           const int* __restrict__ qw) {
    int nt = u >> 5, cg = u & 31;
    int n0 = nt * TILE_N;
    uint32_t stage = sb + (uint32_t)slot * STAGE_BYTES;
    // A: 32 rows x 16 chunks of 16B (swizzled) — depends only on cg
    #pragma unroll
    for (int i = 0; i < 2; i++) {
        int seg = tid + i * 256;
        int r = seg >> 4, cc = seg & 15;
        uint32_t dst = stage + r * 256 + (((uint32_t)cc ^ (uint32_t)(r & 7)) << 4);
        const char* src = (const char*)g_A + ((size_t)r * KTOT + (size_t)cg * TILE_K) * 2 + cc * 16;
        CP16(dst, src);
    }
    // Q: 16 kwords x 32 segs of 16B
    #pragma unroll
    for (int i = 0; i < 2; i++) {
        int seg = tid + i * 256;
        int kw = seg >> 5, ns = seg & 31;
        uint32_t dst = stage + 8192 + kw * 512 + ns * 16;
        const char* src = (const char*)qw + ((size_t)(cg * 16 + kw) * NTOT + n0) * 4 + ns * 16;
        CP16(dst, src);
    }
    CP_COMMIT();
}

__global__ void __launch_bounds__(THREADS, 2) gemm_kernel(
    const int* __restrict__ qw, const float* __restrict__ scales,
    const float* __restrict__ zeros, const float* __restrict__ bias,
    float* __restrict__ out) {
    extern __shared__ __align__(1024) char smem[];
    uint32_t sb = smem_u32(smem);
    int tid = threadIdx.x, wid = tid >> 5, lane = tid & 31;
    float* S_sm = (float*)(smem + SM_S);

    int u0 = (int)(((long long)blockIdx.x * UNITS) / GRID);
    int u1 = (int)(((long long)(blockIdx.x + 1) * UNITS) / GRID);

    if (tid < 32)
        S_sm[tid] = g_Spart[tid * 4] + g_Spart[tid * 4 + 1] +
                    g_Spart[tid * 4 + 2] + g_Spart[tid * 4 + 3];

    // prologue: up to 3 units in flight
    if (u0 + 0 < u1) issue_unit(sb, tid, u0 + 0, 0, qw);
    if (u0 + 1 < u1) issue_unit(sb, tid, u0 + 1, 1, qw);
    if (u0 + 2 < u1) issue_unit(sb, tid, u0 + 2, 2, qw);

    const int lrow = lane & 15;
    const int lcb  = lane >> 4;
    const int j4   = lane & 3;
    const int nrow = lane >> 2;
    const uint32_t sh4 = (uint32_t)(j4 * 4);

    float acc[2][2][4];
    #pragma unroll
    for (int mt = 0; mt < 2; mt++)
        #pragma unroll
        for (int j = 0; j < 2; j++)
            #pragma unroll
            for (int i = 0; i < 4; i++) acc[mt][j][i] = 0.f;

    int seg_nt = u0 >> 5;
    bool seg_first = ((u0 & 31) == 0);

    for (int u = u0; u < u1; u++) {
        // wait so the current unit's group has landed
        if (u + 2 < u1)      asm volatile("cp.async.wait_group 2;" ::: "memory");
        else if (u + 1 < u1) asm volatile("cp.async.wait_group 1;" ::: "memory");
        else                 asm volatile("cp.async.wait_group 0;" ::: "memory");
        __syncthreads();
        if (u + 3 < u1) issue_unit(sb, tid, u + 3, (u + 3 - u0) & (STAGES - 1), qw);

        uint32_t aBase = sb + (uint32_t)((u - u0) & (STAGES - 1)) * STAGE_BYTES;
        uint32_t qBase = aBase + 8192;
        uint32_t q0 = qBase + (uint32_t)(wid * 16 + nrow) * 4;   // j=0 n-slice
        uint32_t q1 = q0 + 8 * 4;                                 // j=1 n-slice
        uint32_t aRow = aBase + (uint32_t)lrow * 256;

        // register double-buffered kk pipeline
        uint32_t a0[2][4], a1[2][4], w[2][4];
        {
            uint32_t cc = (uint32_t)lcb;
            uint32_t ad = aRow + ((cc ^ (uint32_t)(lrow & 7)) << 4);
            ldmx4(a0[0], ad);
            ldmx4(a1[0], ad + 16 * 256);
            w[0][0] = lds32(q0);
            w[0][1] = lds32(q0 + 512);
            w[0][2] = lds32(q1);
            w[0][3] = lds32(q1 + 512);
        }
        #pragma unroll
        for (int kk = 0; kk < 8; kk++) {
            int cur = kk & 1, nx = cur ^ 1;
            if (kk < 7) {
                uint32_t cc = (uint32_t)((kk + 1) * 2 + lcb);
                uint32_t ad = aRow + ((cc ^ (uint32_t)(lrow & 7)) << 4);
                ldmx4(a0[nx], ad);
                ldmx4(a1[nx], ad + 16 * 256);
                w[nx][0] = lds32(q0 + (kk + 1) * 1024);
                w[nx][1] = lds32(q0 + (kk + 1) * 1024 + 512);
                w[nx][2] = lds32(q1 + (kk + 1) * 1024);
                w[nx][3] = lds32(q1 + (kk + 1) * 1024 + 512);
            }
            uint32_t b00 = ((w[cur][0] >> sh4) & 0x000F000Fu) | 0x64006400u;
            uint32_t b01 = ((w[cur][1] >> sh4) & 0x000F000Fu) | 0x64006400u;
            uint32_t b10 = ((w[cur][2] >> sh4) & 0x000F000Fu) | 0x64006400u;
            uint32_t b11 = ((w[cur][3] >> sh4) & 0x000F000Fu) | 0x64006400u;

            mma16816(acc[0][0], a0[cur], b00, b01);
            mma16816(acc[1][0], a1[cur], b00, b01);
            mma16816(acc[0][1], a0[cur], b10, b11);
            mma16816(acc[1][1], a1[cur], b10, b11);
        }

        // flush at segment end (tile boundary or range end)
        bool last = (u + 1 == u1);
        if (last || ((u + 1) >> 5) != seg_nt) {
            int n0 = seg_nt * TILE_N;
            #pragma unroll
            for (int mt = 0; mt < 2; mt++) {
                #pragma unroll
                for (int j = 0; j < 2; j++) {
                    int ncl = wid * 16 + j * 8 + j4 * 2;
                    int col = n0 + ncl;
                    float s0 = __ldg(scales + col), s1 = __ldg(scales + col + 1);
                    int r0 = mt * 16 + nrow;
                    int r1 = r0 + 8;
                    float v00 = s0 * acc[mt][j][0];
                    float v01 = s1 * acc[mt][j][1];
                    float v10 = s0 * acc[mt][j][2];
                    float v11 = s1 * acc[mt][j][3];
                    if (seg_first) {
                        float c0 = fmaf(1024.f, s0, __ldg(zeros + col));
                        float c1 = fmaf(1024.f, s1, __ldg(zeros + col + 1));
                        float b0 = __ldg(bias + col);
                        float b1 = __ldg(bias + col + 1);
                        float S0 = S_sm[r0], S1 = S_sm[r1];
                        v00 += b0 - S0 * c0;
                        v01 += b1 - S0 * c1;
                        v10 += b0 - S1 * c0;
                        v11 += b1 - S1 * c1;
                    }
                    atomicAdd(out + (size_t)r0 * NTOT + col,     v00);
                    atomicAdd(out + (size_t)r0 * NTOT + col + 1, v01);
                    atomicAdd(out + (size_t)r1 * NTOT + col,     v10);
                    atomicAdd(out + (size_t)r1 * NTOT + col + 1, v11);
                    acc[mt][j][0] = acc[mt][j][1] = acc[mt][j][2] = acc[mt][j][3] = 0.f;
                }
            }
            if (!last) {
                seg_nt = (u + 1) >> 5;
                seg_first = true;        // boundary segments start at chunk 0
            }
        }
    }
}

// ---------------------------------------------------------------------------
extern "C" void kernel_launch(void* const* d_in, const int* in_sizes, int n_in,
                              void* d_out, int out_size) {
    const float* x      = (const float*)d_in[0];
    const int*   qw     = (const int*)d_in[1];
    const float* scales = (const float*)d_in[2];
    const float* zeros  = (const float*)d_in[3];
    const float* bias   = (const float*)d_in[4];
    float* out = (float*)d_out;

    cudaFuncSetAttribute(gemm_kernel, cudaFuncAttributeMaxDynamicSharedMemorySize, SMEM_TOTAL);

    prep_kernel<<<128, 128>>>(x, out);
    gemm_kernel<<<GRID, THREADS, SMEM_TOTAL>>>(qw, scales, zeros, bias, out);
}